// round 10
// baseline (speedup 1.0000x reference)
#include <cuda_runtime.h>
#include <cuda_fp16.h>
#include <cstdint>
#include <math.h>

#define Bv      8
#define Sv      512
#define Dv      512
#define WIDTHv  16
#define NPAD    544
#define MQKV    (Bv*NPAD)      // 4352
#define MS      (Bv*Sv)        // 4096
#define M2      (2*MS)         // 8192

#define WOFF_QKV 0
#define WOFF_WO  1572864
#define WOFF_HW  2097152
#define BOFF_QKV 0
#define BOFF_WO  3072
#define BOFF_HW  4096

// ---------------- scratch (half activations/weights) ---------------------------
__device__ __half g_x[MQKV*Dv];
__device__ __half g_qkv[MQKV*3072];
__device__ __half g_attn[2*MQKV*Dv];
__device__ __half g_h0a[M2*Dv];
__device__ __half g_h0b[M2*Dv];
__device__ __half g_wcvt[4194304];
__device__ float  g_bias[8192];

// ---------------- helpers -------------------------------------------------------
__device__ __forceinline__ uint32_t smem_u32(const void* p) {
    uint32_t a;
    asm("{ .reg .u64 t; cvta.to.shared.u64 t, %1; cvt.u32.u64 %0, t; }"
        : "=r"(a) : "l"(p));
    return a;
}
__device__ __forceinline__ void cpa16(uint32_t s, const void* g) {
    asm volatile("cp.async.cg.shared.global [%0], [%1], 16;" :: "r"(s), "l"(g));
}
__device__ __forceinline__ void ldsm4(uint32_t addr, uint32_t& r0, uint32_t& r1,
                                      uint32_t& r2, uint32_t& r3) {
    asm volatile("ldmatrix.sync.aligned.m8n8.x4.shared.b16 {%0,%1,%2,%3}, [%4];"
                 : "=r"(r0), "=r"(r1), "=r"(r2), "=r"(r3) : "r"(addr));
}

// ---------------- prep: weights+biases+pad in ONE kernel --------------------------
__global__ void prep_kernel(
    const float* __restrict__ inp,
    const float* __restrict__ lp,  const float* __restrict__ rp,
    const float* __restrict__ Wq0, const float* __restrict__ Wq1,
    const float* __restrict__ Wo0, const float* __restrict__ Wo1,
    const float* __restrict__ Wh0, const float* __restrict__ Wh1,
    const float* __restrict__ bq0, const float* __restrict__ bq1,
    const float* __restrict__ bo0, const float* __restrict__ bo1,
    const float* __restrict__ bh0, const float* __restrict__ bh1)
{
    int i = blockIdx.x * 256 + threadIdx.x;
    if (i < 4194304) {
        float v;
        if (i < WOFF_WO) {
            int n = i >> 9, k = i & 511;
            int d = n >= 1536;
            const float* W = d ? Wq1 : Wq0;
            v = W[(n - d * 1536) * 512 + k];
        } else if (i < WOFF_HW) {
            int j = i - WOFF_WO;
            int n = j >> 9, k = j & 511;
            int d = n >= 512;
            const float* W = d ? Wo1 : Wo0;
            v = W[(n - d * 512) * 512 + k];
        } else {
            int j = i - WOFF_HW;
            int blk = j >> 19;
            int d = blk >> 1, l = blk & 1;
            int rw = (j >> 9) & 1023, k = j & 511;
            int c = rw >> 1, wh = rw & 1;
            const float* W = d ? Wh1 : Wh0;
            v = W[l * 524288 + (wh * 512 + c) * 512 + k];
        }
        g_wcvt[i] = __float2half_rn(v);
    } else if (i < 4194304 + 8192) {
        int j = i - 4194304;
        float v;
        if (j < BOFF_WO) {
            int d = j >= 1536;
            v = (d ? bq1 : bq0)[j - d * 1536];
        } else if (j < BOFF_HW) {
            int jj = j - BOFF_WO;
            int d = jj >= 512;
            v = (d ? bo1 : bo0)[jj - d * 512];
        } else {
            int jj = j - BOFF_HW;
            int blk = jj >> 10;
            int d = blk >> 1, l = blk & 1;
            int r = jj & 1023;
            int c = r >> 1, wh = r & 1;
            v = (d ? bh1 : bh0)[l * 1024 + wh * 512 + c];
        }
        g_bias[j] = v;
    } else {
        int idx = i - (4194304 + 8192);
        if (idx >= MQKV * Dv) return;
        int d = idx & (Dv - 1);
        int p = (idx / Dv) % NPAD;
        int b = idx / (Dv * NPAD);
        float v;
        if (p < WIDTHv)            v = lp[p * Dv + d];
        else if (p < WIDTHv + Sv)  v = inp[((size_t)b * Sv + (p - WIDTHv)) * Dv + d];
        else                       v = rp[(p - WIDTHv - Sv) * Dv + d];
        g_x[idx] = __float2half_rn(v);
    }
}

// ---------------- fp16 mma GEMM: BK=64, 3 buffers, ldmatrix fragment loads ---------
#define AB2    18432            // 128*72*2 bytes per matrix per stage
#define STGB   36864            // per stage (A+W)

__global__ __launch_bounds__(256, 2) void gemm_mma(
    const __half* __restrict__ A, const __half* __restrict__ W,
    const float* __restrict__ bias, void* __restrict__ Cout,
    int Nn, int amap, long wstride, int bstride,
    int emode, long total, int copies)
{
    extern __shared__ char dsm[];
    uint32_t sbase = smem_u32(dsm);
    int tid = threadIdx.x;
    int m0 = blockIdx.y * 128, n0 = blockIdx.x * 128;

    if (m0 >= 4096) { W += wstride; bias += bstride; }

    long aoff[4]; int woff[4];
    uint32_t soff[4];
#pragma unroll
    for (int i = 0; i < 4; i++) {
        int id = tid + 256 * i;
        int row = id >> 3, seg = id & 7;
        int gm = m0 + row;
        long ar;
        if (amap) {
            int dir = gm >> 12, s = gm & 4095;
            ar = (long)dir * MQKV + (s >> 9) * NPAD + WIDTHv + (s & 511);
        } else ar = gm;
        aoff[i] = ar * 512 + seg * 8;
        woff[i] = (n0 + row) * 512 + seg * 8;
        soff[i] = (uint32_t)(row * 144 + seg * 16);
    }

#pragma unroll
    for (int s = 0; s < 2; s++) {
        uint32_t ab = sbase + (uint32_t)s * STGB;
#pragma unroll
        for (int i = 0; i < 4; i++) {
            cpa16(ab + soff[i],       A + aoff[i] + s * 64);
            cpa16(ab + AB2 + soff[i], W + woff[i] + s * 64);
        }
        asm volatile("cp.async.commit_group;");
    }

    int wid = tid >> 5, lane = tid & 31;
    int wm = wid >> 2, wn = wid & 3;
    int grp = lane >> 2, tig = lane & 3;
    int l8 = lane & 7, q = lane >> 3;

    // ldmatrix x4 per-thread offset (bytes): matrix q -> rows (q&1)*8, k-halves (q>>1)*8.
    // Identical mapping for A and B (both are row×k-contiguous; mma pairs halves along k).
    uint32_t oF = (uint32_t)((l8 + ((q & 1) << 3)) * 72 + ((q >> 1) << 3)) * 2u;

    float acc[4][4][4];
#pragma unroll
    for (int mt = 0; mt < 4; mt++)
#pragma unroll
        for (int nt = 0; nt < 4; nt++)
#pragma unroll
            for (int r = 0; r < 4; r++) acc[mt][nt][r] = 0.f;

    for (int c = 0; c < 8; c++) {
        if (c >= 7) asm volatile("cp.async.wait_group 0;" ::: "memory");
        else        asm volatile("cp.async.wait_group 1;" ::: "memory");
        __syncthreads();
        if (c + 2 < 8) {
            uint32_t ab = sbase + (uint32_t)((c + 2) % 3) * STGB;
            int k0 = (c + 2) * 64;
#pragma unroll
            for (int i = 0; i < 4; i++) {
                cpa16(ab + soff[i],       A + aoff[i] + k0);
                cpa16(ab + AB2 + soff[i], W + woff[i] + k0);
            }
            asm volatile("cp.async.commit_group;");
        }

        uint32_t abase = sbase + (uint32_t)(c % 3) * STGB;
        uint32_t aA = abase + oF + (uint32_t)(wm * 64) * 144u;
        uint32_t aB = abase + AB2 + oF + (uint32_t)(wn * 32) * 144u;

#pragma unroll
        for (int kk = 0; kk < 4; kk++) {
            uint32_t kof = (uint32_t)(kk * 16) * 2u;
            uint32_t a[4][4], b[4][2];
            // A: r0=(m0-7,k0-7)=a0, r1=(m8-15,k0-7)=a1, r2=(m0-7,k8-15)=a2, r3=a3
#pragma unroll
            for (int mt = 0; mt < 4; mt++)
                ldsm4(aA + (uint32_t)(mt * 16) * 144u + kof,
                      a[mt][0], a[mt][1], a[mt][2], a[mt][3]);
            // B (non-trans, same pairing-along-k as A):
            // r0=(n0-7,k0-7)->b[np2][0], r1=(n8-15,k0-7)->b[np2+1][0],
            // r2=(n0-7,k8-15)->b[np2][1], r3=(n8-15,k8-15)->b[np2+1][1]
#pragma unroll
            for (int np = 0; np < 2; np++)
                ldsm4(aB + (uint32_t)(np * 16) * 144u + kof,
                      b[np*2][0], b[np*2+1][0], b[np*2][1], b[np*2+1][1]);
#pragma unroll
            for (int mt = 0; mt < 4; mt++)
#pragma unroll
                for (int nt = 0; nt < 4; nt++) {
                    asm volatile(
                        "mma.sync.aligned.m16n8k16.row.col.f32.f16.f16.f32 "
                        "{%0,%1,%2,%3}, {%4,%5,%6,%7}, {%8,%9}, {%0,%1,%2,%3};"
                        : "+f"(acc[mt][nt][0]), "+f"(acc[mt][nt][1]),
                          "+f"(acc[mt][nt][2]), "+f"(acc[mt][nt][3])
                        : "r"(a[mt][0]), "r"(a[mt][1]), "r"(a[mt][2]), "r"(a[mt][3]),
                          "r"(b[nt][0]), "r"(b[nt][1]));
                }
        }
    }

    if (emode == 0) {
        __half* C = (__half*)Cout;
#pragma unroll
        for (int mt = 0; mt < 4; mt++) {
            int r = m0 + wm * 64 + mt * 16 + grp;
#pragma unroll
            for (int nt = 0; nt < 4; nt++) {
                int col = n0 + wn * 32 + nt * 8 + 2 * tig;
                float b0 = bias[col], b1 = bias[col + 1];
                __half2 p0 = __floats2half2_rn(acc[mt][nt][0] + b0, acc[mt][nt][1] + b1);
                __half2 p1 = __floats2half2_rn(acc[mt][nt][2] + b0, acc[mt][nt][3] + b1);
                *(__half2*)(C + (size_t)r * Nn + col)       = p0;
                *(__half2*)(C + (size_t)(r + 8) * Nn + col) = p1;
            }
        }
    } else {
#pragma unroll
        for (int mt = 0; mt < 4; mt++) {
            int r = m0 + wm * 64 + mt * 16 + grp;
#pragma unroll
            for (int nt = 0; nt < 4; nt++) {
                int col = n0 + wn * 32 + nt * 8 + 2 * tig;
                int cc = col >> 1;
                float b0 = bias[col], b1 = bias[col + 1];
                float nl1 = acc[mt][nt][0] + b0, gv1 = acc[mt][nt][1] + b1;
                float nl2 = acc[mt][nt][2] + b0, gv2 = acc[mt][nt][3] + b1;
                nl1 = nl1 > 0.f ? nl1 : 0.f;
                nl2 = nl2 > 0.f ? nl2 : 0.f;
                float sg1 = 1.f / (1.f + __expf(-gv1));
                float sg2 = 1.f / (1.f + __expf(-gv2));
                float old1 = __half2float(A[(size_t)r * 512 + cc]);
                float old2 = __half2float(A[(size_t)(r + 8) * 512 + cc]);
                float res1 = sg1 * old1 + (1.f - sg1) * nl1;
                float res2 = sg2 * old2 + (1.f - sg2) * nl2;
                if (emode == 1) {
                    __half* C = (__half*)Cout;
                    C[(size_t)r * 512 + cc]       = __float2half_rn(res1);
                    C[(size_t)(r + 8) * 512 + cc] = __float2half_rn(res2);
                } else {
                    float* C = (float*)Cout;
                    int d1 = r >> 12, s1 = r & 4095;
                    int r2 = r + 8;
                    int d2 = r2 >> 12, s2 = r2 & 4095;
                    size_t o1 = (size_t)s1 * 1024 + d1 * 512 + cc;
                    size_t o2 = (size_t)s2 * 1024 + d2 * 512 + cc;
                    C[o1] = res1; C[o2] = res2;
                    if (copies == 2) { C[total + o1] = res1; C[total + o2] = res2; }
                }
            }
        }
    }
}

// ---------------- banded attention: 2 rows/thread, single-pass softmax --------------
__device__ __forceinline__ void ld8h(const __half* p, float* f) {
    uint4 u = *(const uint4*)p;
    float2 t;
    t = __half22float2(*(__half2*)&u.x); f[0] = t.x; f[1] = t.y;
    t = __half22float2(*(__half2*)&u.y); f[2] = t.x; f[3] = t.y;
    t = __half22float2(*(__half2*)&u.z); f[4] = t.x; f[5] = t.y;
    t = __half22float2(*(__half2*)&u.w); f[6] = t.x; f[7] = t.y;
}

__global__ __launch_bounds__(64) void attn_kernel() {
    int blk = blockIdx.x;
    int dir = blk >= (Bv * 272);
    int rem = dir ? blk - Bv * 272 : blk;
    int b = rem / 272;
    int i0 = (rem % 272) * 2;
    int h = threadIdx.x;

    const __half* qkv = g_qkv + (size_t)(b * NPAD) * 3072 + dir * 1536 + h * 8;

    float q[2][8];
#pragma unroll
    for (int r = 0; r < 2; r++) ld8h(qkv + (size_t)(i0 + r) * 3072, q[r]);

    int jbase = dir ? i0 : i0 - WIDTHv - 1;

    float sum[2] = {0, 0};
    float o[2][8];
#pragma unroll
    for (int r = 0; r < 2; r++)
#pragma unroll
        for (int d = 0; d < 8; d++) o[r][d] = 0.f;

#pragma unroll
    for (int jidx = 0; jidx < 19; jidx++) {
        int j = jbase + jidx;
        bool jr = (j >= 0) && (j < NPAD);
        float k[8], v[8];
        if (jr) {
            ld8h(qkv + (size_t)j * 3072 + 512,  k);
            ld8h(qkv + (size_t)j * 3072 + 1024, v);
        }
#pragma unroll
        for (int r = 0; r < 2; r++) {
            int jj = jidx - r;
            if (jj >= 0 && jj < 18 && jr) {
                float s = q[r][0]*k[0] + q[r][1]*k[1] + q[r][2]*k[2] + q[r][3]*k[3]
                        + q[r][4]*k[4] + q[r][5]*k[5] + q[r][6]*k[6] + q[r][7]*k[7];
                float p = __expf(s * 0.35355339059327373f);
                sum[r] += p;
#pragma unroll
                for (int d = 0; d < 8; d++) o[r][d] += p * v[d];
            }
        }
    }
#pragma unroll
    for (int r = 0; r < 2; r++) {
        float inv = 1.f / sum[r];
        uint4 u;
        __half2 h0 = __floats2half2_rn(o[r][0] * inv, o[r][1] * inv);
        __half2 h1 = __floats2half2_rn(o[r][2] * inv, o[r][3] * inv);
        __half2 h2 = __floats2half2_rn(o[r][4] * inv, o[r][5] * inv);
        __half2 h3 = __floats2half2_rn(o[r][6] * inv, o[r][7] * inv);
        u.x = *(uint32_t*)&h0; u.y = *(uint32_t*)&h1;
        u.z = *(uint32_t*)&h2; u.w = *(uint32_t*)&h3;
        *(uint4*)(g_attn + ((size_t)dir * MQKV + b * NPAD + i0 + r) * 512 + h * 8) = u;
    }
}

// ---------------- launcher -----------------------------------------------------------
extern "C" void kernel_launch(void* const* d_in, const int* in_sizes, int n_in,
                              void* d_out, int out_size) {
    __half *xp, *qkvp, *attnp, *h0a, *h0b, *wcp;
    float *bp;
    cudaGetSymbolAddress((void**)&xp,   g_x);
    cudaGetSymbolAddress((void**)&qkvp, g_qkv);
    cudaGetSymbolAddress((void**)&attnp,g_attn);
    cudaGetSymbolAddress((void**)&h0a,  g_h0a);
    cudaGetSymbolAddress((void**)&h0b,  g_h0b);
    cudaGetSymbolAddress((void**)&wcp,  g_wcvt);
    cudaGetSymbolAddress((void**)&bp,   g_bias);

    cudaFuncSetAttribute(gemm_mma, cudaFuncAttributeMaxDynamicSharedMemorySize, 110592);

    long total = (long)MS * 1024;
    int copies = ((long)out_size >= 2 * total) ? 2 : 1;

    int prep_n = 4194304 + 8192 + MQKV * Dv;
    prep_kernel<<<(prep_n + 255) / 256, 256>>>(
        (const float*)d_in[0], (const float*)d_in[1], (const float*)d_in[2],
        (const float*)d_in[3], (const float*)d_in[7],
        (const float*)d_in[5], (const float*)d_in[9],
        (const float*)d_in[11], (const float*)d_in[13],
        (const float*)d_in[4], (const float*)d_in[8],
        (const float*)d_in[6], (const float*)d_in[10],
        (const float*)d_in[12], (const float*)d_in[14]);

    // QKV both dirs: [4352,512] x [3072,512]^T -> half
    gemm_mma<<<dim3(24, 34), 256, 110592>>>(
        xp, wcp + WOFF_QKV, bp + BOFF_QKV, qkvp, 3072,
        0, 0, 0, 0, 0, 0);

    attn_kernel<<<2 * Bv * 272, 64>>>();

    // Wo batched + slice fuse -> h0a (half)
    gemm_mma<<<dim3(4, 64), 256, 110592>>>(
        attnp, wcp + WOFF_WO, bp + BOFF_WO, h0a, 512,
        1, 262144, 512, 0, 0, 0);

    // highway layer 0 (fused gate): h0a -> h0b (half)
    gemm_mma<<<dim3(8, 64), 256, 110592>>>(
        h0a, wcp + WOFF_HW, bp + BOFF_HW, h0b, 1024,
        0, 1048576, 2048, 1, 0, 0);

    // highway layer 1 (fused gate + scatter): h0b -> d_out (float)
    gemm_mma<<<dim3(8, 64), 256, 110592>>>(
        h0b, wcp + WOFF_HW + 524288, bp + BOFF_HW + 1024, d_out, 1024,
        0, 1048576, 2048, 2, total, copies);
}

// round 11
// speedup vs baseline: 1.6037x; 1.6037x over previous
#include <cuda_runtime.h>
#include <cuda_fp16.h>
#include <cstdint>
#include <math.h>

#define Bv      8
#define Sv      512
#define Dv      512
#define WIDTHv  16
#define NPAD    544
#define MQKV    (Bv*NPAD)      // 4352
#define MS      (Bv*Sv)        // 4096
#define M2      (2*MS)         // 8192

#define WOFF_QKV 0
#define WOFF_WO  1572864
#define WOFF_HW  2097152
#define BOFF_QKV 0
#define BOFF_WO  3072
#define BOFF_HW  4096

// ---------------- scratch (half activations/weights) ---------------------------
__device__ __half g_x[MQKV*Dv];
__device__ __half g_qkv[MQKV*3072];
__device__ __half g_attn[2*MQKV*Dv];
__device__ __half g_h0a[M2*Dv];
__device__ __half g_h0b[M2*Dv];
__device__ __half g_wcvt[4194304];
__device__ float  g_bias[8192];

// ---------------- helpers -------------------------------------------------------
__device__ __forceinline__ uint32_t smem_u32(const void* p) {
    uint32_t a;
    asm("{ .reg .u64 t; cvta.to.shared.u64 t, %1; cvt.u32.u64 %0, t; }"
        : "=r"(a) : "l"(p));
    return a;
}
__device__ __forceinline__ void cpa16(uint32_t s, const void* g) {
    asm volatile("cp.async.cg.shared.global [%0], [%1], 16;" :: "r"(s), "l"(g));
}

// ---------------- prep (vectorized, 2 elems/thread) -------------------------------
// ranges: [0, 2097152) weight half2 pairs; [2097152, 2105344) bias scalars;
//         [2105344, 3219456) pad half2 pairs
#define PREP_W2   2097152
#define PREP_B    (PREP_W2 + 8192)
#define PREP_P2   (PREP_B + MQKV*Dv/2)

__global__ void prep_kernel(
    const float* __restrict__ inp,
    const float* __restrict__ lp,  const float* __restrict__ rp,
    const float* __restrict__ Wq0, const float* __restrict__ Wq1,
    const float* __restrict__ Wo0, const float* __restrict__ Wo1,
    const float* __restrict__ Wh0, const float* __restrict__ Wh1,
    const float* __restrict__ bq0, const float* __restrict__ bq1,
    const float* __restrict__ bo0, const float* __restrict__ bo1,
    const float* __restrict__ bh0, const float* __restrict__ bh1)
{
    int t = blockIdx.x * 256 + threadIdx.x;
    if (t < PREP_W2) {
        int i = t * 2;                       // even element index; pair in same row
        const float* src;
        if (i < WOFF_WO) {
            int n = i >> 9, k = i & 511;
            int d = n >= 1536;
            src = (d ? Wq1 : Wq0) + (n - d * 1536) * 512 + k;
        } else if (i < WOFF_HW) {
            int j = i - WOFF_WO;
            int n = j >> 9, k = j & 511;
            int d = n >= 512;
            src = (d ? Wo1 : Wo0) + (n - d * 512) * 512 + k;
        } else {
            int j = i - WOFF_HW;
            int blk = j >> 19;
            int d = blk >> 1, l = blk & 1;
            int rw = (j >> 9) & 1023, k = j & 511;
            int c = rw >> 1, wh = rw & 1;
            src = (d ? Wh1 : Wh0) + l * 524288 + (wh * 512 + c) * 512 + k;
        }
        float2 v = *(const float2*)src;
        *(__half2*)(g_wcvt + i) = __floats2half2_rn(v.x, v.y);
    } else if (t < PREP_B) {
        int j = t - PREP_W2;
        float v;
        if (j < BOFF_WO) {
            int d = j >= 1536;
            v = (d ? bq1 : bq0)[j - d * 1536];
        } else if (j < BOFF_HW) {
            int jj = j - BOFF_WO;
            int d = jj >= 512;
            v = (d ? bo1 : bo0)[jj - d * 512];
        } else {
            int jj = j - BOFF_HW;
            int blk = jj >> 10;
            int d = blk >> 1, l = blk & 1;
            int r = jj & 1023;
            int c = r >> 1, wh = r & 1;
            v = (d ? bh1 : bh0)[l * 1024 + wh * 512 + c];
        }
        g_bias[j] = v;
    } else if (t < PREP_P2) {
        int idx = (t - PREP_B) * 2;
        int d = idx & (Dv - 1);
        int p = (idx / Dv) % NPAD;
        int b = idx / (Dv * NPAD);
        const float* src;
        if (p < WIDTHv)            src = lp + p * Dv + d;
        else if (p < WIDTHv + Sv)  src = inp + ((size_t)b * Sv + (p - WIDTHv)) * Dv + d;
        else                       src = rp + (p - WIDTHv - Sv) * Dv + d;
        float2 v = *(const float2*)src;
        *(__half2*)(g_x + idx) = __floats2half2_rn(v.x, v.y);
    }
}

// ---------------- fp16 mma GEMM: BK=64, 8 chunks, 3 buffers, scalar LDS frags ------
// (round-8 configuration: best measured; ldmatrix variant regressed — do not re-add)
#define AB2    18432            // 128*72*2 bytes per matrix per stage
#define STGB   36864            // per stage (A+W)

__global__ __launch_bounds__(256, 2) void gemm_mma(
    const __half* __restrict__ A, const __half* __restrict__ W,
    const float* __restrict__ bias, void* __restrict__ Cout,
    int Nn, int amap, long wstride, int bstride,
    int emode, long total, int copies)
{
    extern __shared__ char dsm[];
    uint32_t sbase = smem_u32(dsm);
    int tid = threadIdx.x;
    int m0 = blockIdx.y * 128, n0 = blockIdx.x * 128;

    if (m0 >= 4096) { W += wstride; bias += bstride; }

    long aoff[4]; int woff[4];
    uint32_t soff[4];
#pragma unroll
    for (int i = 0; i < 4; i++) {
        int id = tid + 256 * i;
        int row = id >> 3, seg = id & 7;
        int gm = m0 + row;
        long ar;
        if (amap) {
            int dir = gm >> 12, s = gm & 4095;
            ar = (long)dir * MQKV + (s >> 9) * NPAD + WIDTHv + (s & 511);
        } else ar = gm;
        aoff[i] = ar * 512 + seg * 8;
        woff[i] = (n0 + row) * 512 + seg * 8;
        soff[i] = (uint32_t)(row * 144 + seg * 16);
    }

#pragma unroll
    for (int s = 0; s < 2; s++) {
        uint32_t ab = sbase + (uint32_t)s * STGB;
#pragma unroll
        for (int i = 0; i < 4; i++) {
            cpa16(ab + soff[i],       A + aoff[i] + s * 64);
            cpa16(ab + AB2 + soff[i], W + woff[i] + s * 64);
        }
        asm volatile("cp.async.commit_group;");
    }

    int wid = tid >> 5, lane = tid & 31;
    int wm = wid >> 2, wn = wid & 3;
    int grp = lane >> 2, tig = lane & 3;

    float acc[4][4][4];
#pragma unroll
    for (int mt = 0; mt < 4; mt++)
#pragma unroll
        for (int nt = 0; nt < 4; nt++)
#pragma unroll
            for (int r = 0; r < 4; r++) acc[mt][nt][r] = 0.f;

    for (int c = 0; c < 8; c++) {
        if (c >= 7) asm volatile("cp.async.wait_group 0;" ::: "memory");
        else        asm volatile("cp.async.wait_group 1;" ::: "memory");
        __syncthreads();
        if (c + 2 < 8) {
            uint32_t ab = sbase + (uint32_t)((c + 2) % 3) * STGB;
            int k0 = (c + 2) * 64;
#pragma unroll
            for (int i = 0; i < 4; i++) {
                cpa16(ab + soff[i],       A + aoff[i] + k0);
                cpa16(ab + AB2 + soff[i], W + woff[i] + k0);
            }
            asm volatile("cp.async.commit_group;");
        }

        const uint32_t* asu = (const uint32_t*)(dsm + (size_t)(c % 3) * STGB);
        const uint32_t* wsu = asu + AB2 / 4;

#pragma unroll
        for (int kk = 0; kk < 4; kk++) {
            int kb = tig + kk * 8;
            uint32_t a[4][4], b[4][2];
#pragma unroll
            for (int mt = 0; mt < 4; mt++) {
                int r = wm * 64 + mt * 16 + grp;
                a[mt][0] = asu[r * 36 + kb];
                a[mt][1] = asu[(r + 8) * 36 + kb];
                a[mt][2] = asu[r * 36 + kb + 4];
                a[mt][3] = asu[(r + 8) * 36 + kb + 4];
            }
#pragma unroll
            for (int nt = 0; nt < 4; nt++) {
                int n = wn * 32 + nt * 8 + grp;
                b[nt][0] = wsu[n * 36 + kb];
                b[nt][1] = wsu[n * 36 + kb + 4];
            }
#pragma unroll
            for (int mt = 0; mt < 4; mt++)
#pragma unroll
                for (int nt = 0; nt < 4; nt++) {
                    asm volatile(
                        "mma.sync.aligned.m16n8k16.row.col.f32.f16.f16.f32 "
                        "{%0,%1,%2,%3}, {%4,%5,%6,%7}, {%8,%9}, {%0,%1,%2,%3};"
                        : "+f"(acc[mt][nt][0]), "+f"(acc[mt][nt][1]),
                          "+f"(acc[mt][nt][2]), "+f"(acc[mt][nt][3])
                        : "r"(a[mt][0]), "r"(a[mt][1]), "r"(a[mt][2]), "r"(a[mt][3]),
                          "r"(b[nt][0]), "r"(b[nt][1]));
                }
        }
    }

    if (emode == 0) {
        __half* C = (__half*)Cout;
#pragma unroll
        for (int mt = 0; mt < 4; mt++) {
            int r = m0 + wm * 64 + mt * 16 + grp;
#pragma unroll
            for (int nt = 0; nt < 4; nt++) {
                int col = n0 + wn * 32 + nt * 8 + 2 * tig;
                float b0 = bias[col], b1 = bias[col + 1];
                __half2 p0 = __floats2half2_rn(acc[mt][nt][0] + b0, acc[mt][nt][1] + b1);
                __half2 p1 = __floats2half2_rn(acc[mt][nt][2] + b0, acc[mt][nt][3] + b1);
                *(__half2*)(C + (size_t)r * Nn + col)       = p0;
                *(__half2*)(C + (size_t)(r + 8) * Nn + col) = p1;
            }
        }
    } else {
#pragma unroll
        for (int mt = 0; mt < 4; mt++) {
            int r = m0 + wm * 64 + mt * 16 + grp;
#pragma unroll
            for (int nt = 0; nt < 4; nt++) {
                int col = n0 + wn * 32 + nt * 8 + 2 * tig;
                int cc = col >> 1;
                float b0 = bias[col], b1 = bias[col + 1];
                float nl1 = acc[mt][nt][0] + b0, gv1 = acc[mt][nt][1] + b1;
                float nl2 = acc[mt][nt][2] + b0, gv2 = acc[mt][nt][3] + b1;
                nl1 = nl1 > 0.f ? nl1 : 0.f;
                nl2 = nl2 > 0.f ? nl2 : 0.f;
                float sg1 = 1.f / (1.f + __expf(-gv1));
                float sg2 = 1.f / (1.f + __expf(-gv2));
                float old1 = __half2float(A[(size_t)r * 512 + cc]);
                float old2 = __half2float(A[(size_t)(r + 8) * 512 + cc]);
                float res1 = sg1 * old1 + (1.f - sg1) * nl1;
                float res2 = sg2 * old2 + (1.f - sg2) * nl2;
                if (emode == 1) {
                    __half* C = (__half*)Cout;
                    C[(size_t)r * 512 + cc]       = __float2half_rn(res1);
                    C[(size_t)(r + 8) * 512 + cc] = __float2half_rn(res2);
                } else {
                    float* C = (float*)Cout;
                    int d1 = r >> 12, s1 = r & 4095;
                    int r2 = r + 8;
                    int d2 = r2 >> 12, s2 = r2 & 4095;
                    size_t o1 = (size_t)s1 * 1024 + d1 * 512 + cc;
                    size_t o2 = (size_t)s2 * 1024 + d2 * 512 + cc;
                    C[o1] = res1; C[o2] = res2;
                    if (copies == 2) { C[total + o1] = res1; C[total + o2] = res2; }
                }
            }
        }
    }
}

// ---------------- banded attention: 2 rows/thread, single-pass softmax --------------
__device__ __forceinline__ void ld8h(const __half* p, float* f) {
    uint4 u = *(const uint4*)p;
    float2 t;
    t = __half22float2(*(__half2*)&u.x); f[0] = t.x; f[1] = t.y;
    t = __half22float2(*(__half2*)&u.y); f[2] = t.x; f[3] = t.y;
    t = __half22float2(*(__half2*)&u.z); f[4] = t.x; f[5] = t.y;
    t = __half22float2(*(__half2*)&u.w); f[6] = t.x; f[7] = t.y;
}

__global__ __launch_bounds__(64) void attn_kernel() {
    int blk = blockIdx.x;
    int dir = blk >= (Bv * 272);
    int rem = dir ? blk - Bv * 272 : blk;
    int b = rem / 272;
    int i0 = (rem % 272) * 2;
    int h = threadIdx.x;

    const __half* qkv = g_qkv + (size_t)(b * NPAD) * 3072 + dir * 1536 + h * 8;

    float q[2][8];
#pragma unroll
    for (int r = 0; r < 2; r++) ld8h(qkv + (size_t)(i0 + r) * 3072, q[r]);

    int jbase = dir ? i0 : i0 - WIDTHv - 1;

    float sum[2] = {0, 0};
    float o[2][8];
#pragma unroll
    for (int r = 0; r < 2; r++)
#pragma unroll
        for (int d = 0; d < 8; d++) o[r][d] = 0.f;

#pragma unroll
    for (int jidx = 0; jidx < 19; jidx++) {
        int j = jbase + jidx;
        bool jr = (j >= 0) && (j < NPAD);
        float k[8], v[8];
        if (jr) {
            ld8h(qkv + (size_t)j * 3072 + 512,  k);
            ld8h(qkv + (size_t)j * 3072 + 1024, v);
        }
#pragma unroll
        for (int r = 0; r < 2; r++) {
            int jj = jidx - r;
            if (jj >= 0 && jj < 18 && jr) {
                float s = q[r][0]*k[0] + q[r][1]*k[1] + q[r][2]*k[2] + q[r][3]*k[3]
                        + q[r][4]*k[4] + q[r][5]*k[5] + q[r][6]*k[6] + q[r][7]*k[7];
                float p = __expf(s * 0.35355339059327373f);
                sum[r] += p;
#pragma unroll
                for (int d = 0; d < 8; d++) o[r][d] += p * v[d];
            }
        }
    }
#pragma unroll
    for (int r = 0; r < 2; r++) {
        float inv = 1.f / sum[r];
        uint4 u;
        __half2 h0 = __floats2half2_rn(o[r][0] * inv, o[r][1] * inv);
        __half2 h1 = __floats2half2_rn(o[r][2] * inv, o[r][3] * inv);
        __half2 h2 = __floats2half2_rn(o[r][4] * inv, o[r][5] * inv);
        __half2 h3 = __floats2half2_rn(o[r][6] * inv, o[r][7] * inv);
        u.x = *(uint32_t*)&h0; u.y = *(uint32_t*)&h1;
        u.z = *(uint32_t*)&h2; u.w = *(uint32_t*)&h3;
        *(uint4*)(g_attn + ((size_t)dir * MQKV + b * NPAD + i0 + r) * 512 + h * 8) = u;
    }
}

// ---------------- launcher -----------------------------------------------------------
extern "C" void kernel_launch(void* const* d_in, const int* in_sizes, int n_in,
                              void* d_out, int out_size) {
    __half *xp, *qkvp, *attnp, *h0a, *h0b, *wcp;
    float *bp;
    cudaGetSymbolAddress((void**)&xp,   g_x);
    cudaGetSymbolAddress((void**)&qkvp, g_qkv);
    cudaGetSymbolAddress((void**)&attnp,g_attn);
    cudaGetSymbolAddress((void**)&h0a,  g_h0a);
    cudaGetSymbolAddress((void**)&h0b,  g_h0b);
    cudaGetSymbolAddress((void**)&wcp,  g_wcvt);
    cudaGetSymbolAddress((void**)&bp,   g_bias);

    cudaFuncSetAttribute(gemm_mma, cudaFuncAttributeMaxDynamicSharedMemorySize, 110592);

    long total = (long)MS * 1024;
    int copies = ((long)out_size >= 2 * total) ? 2 : 1;

    prep_kernel<<<(PREP_P2 + 255) / 256, 256>>>(
        (const float*)d_in[0], (const float*)d_in[1], (const float*)d_in[2],
        (const float*)d_in[3], (const float*)d_in[7],
        (const float*)d_in[5], (const float*)d_in[9],
        (const float*)d_in[11], (const float*)d_in[13],
        (const float*)d_in[4], (const float*)d_in[8],
        (const float*)d_in[6], (const float*)d_in[10],
        (const float*)d_in[12], (const float*)d_in[14]);

    // QKV both dirs: [4352,512] x [3072,512]^T -> half
    gemm_mma<<<dim3(24, 34), 256, 110592>>>(
        xp, wcp + WOFF_QKV, bp + BOFF_QKV, qkvp, 3072,
        0, 0, 0, 0, 0, 0);

    attn_kernel<<<2 * Bv * 272, 64>>>();

    // Wo batched + slice fuse -> h0a (half)
    gemm_mma<<<dim3(4, 64), 256, 110592>>>(
        attnp, wcp + WOFF_WO, bp + BOFF_WO, h0a, 512,
        1, 262144, 512, 0, 0, 0);

    // highway layer 0 (fused gate): h0a -> h0b (half)
    gemm_mma<<<dim3(8, 64), 256, 110592>>>(
        h0a, wcp + WOFF_HW, bp + BOFF_HW, h0b, 1024,
        0, 1048576, 2048, 1, 0, 0);

    // highway layer 1 (fused gate + scatter): h0b -> d_out (float)
    gemm_mma<<<dim3(8, 64), 256, 110592>>>(
        h0b, wcp + WOFF_HW + 524288, bp + BOFF_HW + 1024, d_out, 1024,
        0, 1048576, 2048, 2, total, copies);
}

// round 12
// speedup vs baseline: 1.6518x; 1.0300x over previous
#include <cuda_runtime.h>
#include <cuda_fp16.h>
#include <cstdint>
#include <math.h>

#define Bv      8
#define Sv      512
#define Dv      512
#define WIDTHv  16
#define NPAD    544
#define MQKV    (Bv*NPAD)      // 4352
#define MS      (Bv*Sv)        // 4096
#define M2      (2*MS)         // 8192

#define WOFF_QKV 0
#define WOFF_WO  1572864
#define WOFF_HW  2097152
#define BOFF_QKV 0
#define BOFF_WO  3072
#define BOFF_HW  4096

// ---------------- scratch (half activations/weights) ---------------------------
__device__ __half g_x[MQKV*Dv];
__device__ __half g_qkv[MQKV*3072];
__device__ __half g_attn[2*MQKV*Dv];
__device__ __half g_h0a[M2*Dv];
__device__ __half g_h0b[M2*Dv];
__device__ __half g_wcvt[4194304];
__device__ float  g_bias[8192];

// ---------------- helpers -------------------------------------------------------
__device__ __forceinline__ uint32_t smem_u32(const void* p) {
    uint32_t a;
    asm("{ .reg .u64 t; cvta.to.shared.u64 t, %1; cvt.u32.u64 %0, t; }"
        : "=r"(a) : "l"(p));
    return a;
}
__device__ __forceinline__ void cpa16(uint32_t s, const void* g) {
    asm volatile("cp.async.cg.shared.global [%0], [%1], 16;" :: "r"(s), "l"(g));
}

// ---------------- prep (vectorized, 2 elems/thread) -------------------------------
#define PREP_W2   2097152
#define PREP_B    (PREP_W2 + 8192)
#define PREP_P2   (PREP_B + MQKV*Dv/2)

__global__ void prep_kernel(
    const float* __restrict__ inp,
    const float* __restrict__ lp,  const float* __restrict__ rp,
    const float* __restrict__ Wq0, const float* __restrict__ Wq1,
    const float* __restrict__ Wo0, const float* __restrict__ Wo1,
    const float* __restrict__ Wh0, const float* __restrict__ Wh1,
    const float* __restrict__ bq0, const float* __restrict__ bq1,
    const float* __restrict__ bo0, const float* __restrict__ bo1,
    const float* __restrict__ bh0, const float* __restrict__ bh1)
{
    int t = blockIdx.x * 256 + threadIdx.x;
    if (t < PREP_W2) {
        int i = t * 2;
        const float* src;
        if (i < WOFF_WO) {
            int n = i >> 9, k = i & 511;
            int d = n >= 1536;
            src = (d ? Wq1 : Wq0) + (n - d * 1536) * 512 + k;
        } else if (i < WOFF_HW) {
            int j = i - WOFF_WO;
            int n = j >> 9, k = j & 511;
            int d = n >= 512;
            src = (d ? Wo1 : Wo0) + (n - d * 512) * 512 + k;
        } else {
            int j = i - WOFF_HW;
            int blk = j >> 19;
            int d = blk >> 1, l = blk & 1;
            int rw = (j >> 9) & 1023, k = j & 511;
            int c = rw >> 1, wh = rw & 1;
            src = (d ? Wh1 : Wh0) + l * 524288 + (wh * 512 + c) * 512 + k;
        }
        float2 v = *(const float2*)src;
        *(__half2*)(g_wcvt + i) = __floats2half2_rn(v.x, v.y);
    } else if (t < PREP_B) {
        int j = t - PREP_W2;
        float v;
        if (j < BOFF_WO) {
            int d = j >= 1536;
            v = (d ? bq1 : bq0)[j - d * 1536];
        } else if (j < BOFF_HW) {
            int jj = j - BOFF_WO;
            int d = jj >= 512;
            v = (d ? bo1 : bo0)[jj - d * 512];
        } else {
            int jj = j - BOFF_HW;
            int blk = jj >> 10;
            int d = blk >> 1, l = blk & 1;
            int r = jj & 1023;
            int c = r >> 1, wh = r & 1;
            v = (d ? bh1 : bh0)[l * 1024 + wh * 512 + c];
        }
        g_bias[j] = v;
    } else if (t < PREP_P2) {
        int idx = (t - PREP_B) * 2;
        int d = idx & (Dv - 1);
        int p = (idx / Dv) % NPAD;
        int b = idx / (Dv * NPAD);
        const float* src;
        if (p < WIDTHv)            src = lp + p * Dv + d;
        else if (p < WIDTHv + Sv)  src = inp + ((size_t)b * Sv + (p - WIDTHv)) * Dv + d;
        else                       src = rp + (p - WIDTHv - Sv) * Dv + d;
        float2 v = *(const float2*)src;
        *(__half2*)(g_x + idx) = __floats2half2_rn(v.x, v.y);
    }
}

// ---------------- fp16 mma GEMM: BM=128 BN=64 BK=64, 128 thr, 2-stage --------------
// 4 CTAs/SM (regs ~126*128*4 = 64.5K; smem 55.3KB*4 = 221KB): decoupled sync domains.
#define ABYT   18432            // A per stage: 128*72*2
#define BBYT   9216             // B per stage: 64*72*2
#define STGB   27648            // per stage (A+B)

__global__ __launch_bounds__(128, 4) void gemm_mma(
    const __half* __restrict__ A, const __half* __restrict__ W,
    const float* __restrict__ bias, void* __restrict__ Cout,
    int Nn, int amap, long wstride, int bstride,
    int emode, long total, int copies)
{
    extern __shared__ char dsm[];
    uint32_t sbase = smem_u32(dsm);
    int tid = threadIdx.x;
    int m0 = blockIdx.y * 128, n0 = blockIdx.x * 64;

    if (m0 >= 4096) { W += wstride; bias += bstride; }

    // global->smem plan: A 8 cpa16/thread, B 4 cpa16/thread per chunk
    long aoff[8]; int woff[4];
    uint32_t sa[8], sw[4];
#pragma unroll
    for (int i = 0; i < 8; i++) {
        int id = tid + 128 * i;
        int row = id >> 3, seg = id & 7;
        int gm = m0 + row;
        long ar;
        if (amap) {
            int dir = gm >> 12, s = gm & 4095;
            ar = (long)dir * MQKV + (s >> 9) * NPAD + WIDTHv + (s & 511);
        } else ar = gm;
        aoff[i] = ar * 512 + seg * 8;
        sa[i] = (uint32_t)(row * 144 + seg * 16);
    }
#pragma unroll
    for (int i = 0; i < 4; i++) {
        int id = tid + 128 * i;
        int row = id >> 3, seg = id & 7;
        woff[i] = (n0 + row) * 512 + seg * 8;
        sw[i] = (uint32_t)(row * 144 + seg * 16);
    }

    // prologue: chunks 0,1 -> buffers 0,1
#pragma unroll
    for (int s = 0; s < 2; s++) {
        uint32_t ab = sbase + (uint32_t)s * STGB;
#pragma unroll
        for (int i = 0; i < 8; i++) cpa16(ab + sa[i],        A + aoff[i] + s * 64);
#pragma unroll
        for (int i = 0; i < 4; i++) cpa16(ab + ABYT + sw[i], W + woff[i] + s * 64);
        asm volatile("cp.async.commit_group;");
    }

    int wid = tid >> 5, lane = tid & 31;
    int wm = wid >> 1, wn = wid & 1;          // 2(m) x 2(n); warp tile 64x32
    int grp = lane >> 2, tig = lane & 3;

    float acc[4][4][4];
#pragma unroll
    for (int mt = 0; mt < 4; mt++)
#pragma unroll
        for (int nt = 0; nt < 4; nt++)
#pragma unroll
            for (int r = 0; r < 4; r++) acc[mt][nt][r] = 0.f;

    for (int c = 0; c < 8; c++) {
        if (c >= 7) asm volatile("cp.async.wait_group 0;" ::: "memory");
        else        asm volatile("cp.async.wait_group 1;" ::: "memory");
        __syncthreads();

        const uint32_t* asu = (const uint32_t*)(dsm + (size_t)(c & 1) * STGB);
        const uint32_t* wsu = asu + ABYT / 4;

#pragma unroll
        for (int kk = 0; kk < 4; kk++) {
            int kb = tig + kk * 8;
            uint32_t a[4][4], b[4][2];
#pragma unroll
            for (int mt = 0; mt < 4; mt++) {
                int r = wm * 64 + mt * 16 + grp;
                a[mt][0] = asu[r * 36 + kb];
                a[mt][1] = asu[(r + 8) * 36 + kb];
                a[mt][2] = asu[r * 36 + kb + 4];
                a[mt][3] = asu[(r + 8) * 36 + kb + 4];
            }
#pragma unroll
            for (int nt = 0; nt < 4; nt++) {
                int n = wn * 32 + nt * 8 + grp;
                b[nt][0] = wsu[n * 36 + kb];
                b[nt][1] = wsu[n * 36 + kb + 4];
            }
#pragma unroll
            for (int mt = 0; mt < 4; mt++)
#pragma unroll
                for (int nt = 0; nt < 4; nt++) {
                    asm volatile(
                        "mma.sync.aligned.m16n8k16.row.col.f32.f16.f16.f32 "
                        "{%0,%1,%2,%3}, {%4,%5,%6,%7}, {%8,%9}, {%0,%1,%2,%3};"
                        : "+f"(acc[mt][nt][0]), "+f"(acc[mt][nt][1]),
                          "+f"(acc[mt][nt][2]), "+f"(acc[mt][nt][3])
                        : "r"(a[mt][0]), "r"(a[mt][1]), "r"(a[mt][2]), "r"(a[mt][3]),
                          "r"(b[nt][0]), "r"(b[nt][1]));
                }
        }
        __syncthreads();

        if (c + 2 < 8) {
            uint32_t ab = sbase + (uint32_t)(c & 1) * STGB;
            int k0 = (c + 2) * 64;
#pragma unroll
            for (int i = 0; i < 8; i++) cpa16(ab + sa[i],        A + aoff[i] + k0);
#pragma unroll
            for (int i = 0; i < 4; i++) cpa16(ab + ABYT + sw[i], W + woff[i] + k0);
            asm volatile("cp.async.commit_group;");
        }
    }

    if (emode == 0) {
        __half* C = (__half*)Cout;
#pragma unroll
        for (int mt = 0; mt < 4; mt++) {
            int r = m0 + wm * 64 + mt * 16 + grp;
#pragma unroll
            for (int nt = 0; nt < 4; nt++) {
                int col = n0 + wn * 32 + nt * 8 + 2 * tig;
                float b0 = bias[col], b1 = bias[col + 1];
                __half2 p0 = __floats2half2_rn(acc[mt][nt][0] + b0, acc[mt][nt][1] + b1);
                __half2 p1 = __floats2half2_rn(acc[mt][nt][2] + b0, acc[mt][nt][3] + b1);
                *(__half2*)(C + (size_t)r * Nn + col)       = p0;
                *(__half2*)(C + (size_t)(r + 8) * Nn + col) = p1;
            }
        }
    } else {
#pragma unroll
        for (int mt = 0; mt < 4; mt++) {
            int r = m0 + wm * 64 + mt * 16 + grp;
#pragma unroll
            for (int nt = 0; nt < 4; nt++) {
                int col = n0 + wn * 32 + nt * 8 + 2 * tig;
                int cc = col >> 1;
                float b0 = bias[col], b1 = bias[col + 1];
                float nl1 = acc[mt][nt][0] + b0, gv1 = acc[mt][nt][1] + b1;
                float nl2 = acc[mt][nt][2] + b0, gv2 = acc[mt][nt][3] + b1;
                nl1 = nl1 > 0.f ? nl1 : 0.f;
                nl2 = nl2 > 0.f ? nl2 : 0.f;
                float sg1 = 1.f / (1.f + __expf(-gv1));
                float sg2 = 1.f / (1.f + __expf(-gv2));
                float old1 = __half2float(A[(size_t)r * 512 + cc]);
                float old2 = __half2float(A[(size_t)(r + 8) * 512 + cc]);
                float res1 = sg1 * old1 + (1.f - sg1) * nl1;
                float res2 = sg2 * old2 + (1.f - sg2) * nl2;
                if (emode == 1) {
                    __half* C = (__half*)Cout;
                    C[(size_t)r * 512 + cc]       = __float2half_rn(res1);
                    C[(size_t)(r + 8) * 512 + cc] = __float2half_rn(res2);
                } else {
                    float* C = (float*)Cout;
                    int d1 = r >> 12, s1 = r & 4095;
                    int r2 = r + 8;
                    int d2 = r2 >> 12, s2 = r2 & 4095;
                    size_t o1 = (size_t)s1 * 1024 + d1 * 512 + cc;
                    size_t o2 = (size_t)s2 * 1024 + d2 * 512 + cc;
                    C[o1] = res1; C[o2] = res2;
                    if (copies == 2) { C[total + o1] = res1; C[total + o2] = res2; }
                }
            }
        }
    }
}

// ---------------- banded attention: 2 rows/thread, single-pass softmax --------------
__device__ __forceinline__ void ld8h(const __half* p, float* f) {
    uint4 u = *(const uint4*)p;
    float2 t;
    t = __half22float2(*(__half2*)&u.x); f[0] = t.x; f[1] = t.y;
    t = __half22float2(*(__half2*)&u.y); f[2] = t.x; f[3] = t.y;
    t = __half22float2(*(__half2*)&u.z); f[4] = t.x; f[5] = t.y;
    t = __half22float2(*(__half2*)&u.w); f[6] = t.x; f[7] = t.y;
}

__global__ __launch_bounds__(64) void attn_kernel() {
    int blk = blockIdx.x;
    int dir = blk >= (Bv * 272);
    int rem = dir ? blk - Bv * 272 : blk;
    int b = rem / 272;
    int i0 = (rem % 272) * 2;
    int h = threadIdx.x;

    const __half* qkv = g_qkv + (size_t)(b * NPAD) * 3072 + dir * 1536 + h * 8;

    float q[2][8];
#pragma unroll
    for (int r = 0; r < 2; r++) ld8h(qkv + (size_t)(i0 + r) * 3072, q[r]);

    int jbase = dir ? i0 : i0 - WIDTHv - 1;

    float sum[2] = {0, 0};
    float o[2][8];
#pragma unroll
    for (int r = 0; r < 2; r++)
#pragma unroll
        for (int d = 0; d < 8; d++) o[r][d] = 0.f;

#pragma unroll
    for (int jidx = 0; jidx < 19; jidx++) {
        int j = jbase + jidx;
        bool jr = (j >= 0) && (j < NPAD);
        float k[8], v[8];
        if (jr) {
            ld8h(qkv + (size_t)j * 3072 + 512,  k);
            ld8h(qkv + (size_t)j * 3072 + 1024, v);
        }
#pragma unroll
        for (int r = 0; r < 2; r++) {
            int jj = jidx - r;
            if (jj >= 0 && jj < 18 && jr) {
                float s = q[r][0]*k[0] + q[r][1]*k[1] + q[r][2]*k[2] + q[r][3]*k[3]
                        + q[r][4]*k[4] + q[r][5]*k[5] + q[r][6]*k[6] + q[r][7]*k[7];
                float p = __expf(s * 0.35355339059327373f);
                sum[r] += p;
#pragma unroll
                for (int d = 0; d < 8; d++) o[r][d] += p * v[d];
            }
        }
    }
#pragma unroll
    for (int r = 0; r < 2; r++) {
        float inv = 1.f / sum[r];
        uint4 u;
        __half2 h0 = __floats2half2_rn(o[r][0] * inv, o[r][1] * inv);
        __half2 h1 = __floats2half2_rn(o[r][2] * inv, o[r][3] * inv);
        __half2 h2 = __floats2half2_rn(o[r][4] * inv, o[r][5] * inv);
        __half2 h3 = __floats2half2_rn(o[r][6] * inv, o[r][7] * inv);
        u.x = *(uint32_t*)&h0; u.y = *(uint32_t*)&h1;
        u.z = *(uint32_t*)&h2; u.w = *(uint32_t*)&h3;
        *(uint4*)(g_attn + ((size_t)dir * MQKV + b * NPAD + i0 + r) * 512 + h * 8) = u;
    }
}

// ---------------- launcher -----------------------------------------------------------
extern "C" void kernel_launch(void* const* d_in, const int* in_sizes, int n_in,
                              void* d_out, int out_size) {
    __half *xp, *qkvp, *attnp, *h0a, *h0b, *wcp;
    float *bp;
    cudaGetSymbolAddress((void**)&xp,   g_x);
    cudaGetSymbolAddress((void**)&qkvp, g_qkv);
    cudaGetSymbolAddress((void**)&attnp,g_attn);
    cudaGetSymbolAddress((void**)&h0a,  g_h0a);
    cudaGetSymbolAddress((void**)&h0b,  g_h0b);
    cudaGetSymbolAddress((void**)&wcp,  g_wcvt);
    cudaGetSymbolAddress((void**)&bp,   g_bias);

    cudaFuncSetAttribute(gemm_mma, cudaFuncAttributeMaxDynamicSharedMemorySize, 55296);

    long total = (long)MS * 1024;
    int copies = ((long)out_size >= 2 * total) ? 2 : 1;

    prep_kernel<<<(PREP_P2 + 255) / 256, 256>>>(
        (const float*)d_in[0], (const float*)d_in[1], (const float*)d_in[2],
        (const float*)d_in[3], (const float*)d_in[7],
        (const float*)d_in[5], (const float*)d_in[9],
        (const float*)d_in[11], (const float*)d_in[13],
        (const float*)d_in[4], (const float*)d_in[8],
        (const float*)d_in[6], (const float*)d_in[10],
        (const float*)d_in[12], (const float*)d_in[14]);

    // QKV both dirs: [4352,512] x [3072,512]^T -> half  (BN=64)
    gemm_mma<<<dim3(48, 34), 128, 55296>>>(
        xp, wcp + WOFF_QKV, bp + BOFF_QKV, qkvp, 3072,
        0, 0, 0, 0, 0, 0);

    attn_kernel<<<2 * Bv * 272, 64>>>();

    // Wo batched + slice fuse -> h0a (half)
    gemm_mma<<<dim3(8, 64), 128, 55296>>>(
        attnp, wcp + WOFF_WO, bp + BOFF_WO, h0a, 512,
        1, 262144, 512, 0, 0, 0);

    // highway layer 0 (fused gate): h0a -> h0b (half)
    gemm_mma<<<dim3(16, 64), 128, 55296>>>(
        h0a, wcp + WOFF_HW, bp + BOFF_HW, h0b, 1024,
        0, 1048576, 2048, 1, 0, 0);

    // highway layer 1 (fused gate + scatter): h0b -> d_out (float)
    gemm_mma<<<dim3(16, 64), 128, 55296>>>(
        h0b, wcp + WOFF_HW + 524288, bp + BOFF_HW + 1024, d_out, 1024,
        0, 1048576, 2048, 2, total, copies);
}

// round 13
// speedup vs baseline: 1.7076x; 1.0338x over previous
#include <cuda_runtime.h>
#include <cuda_fp16.h>
#include <cstdint>
#include <math.h>

#define Bv      8
#define Sv      512
#define Dv      512
#define WIDTHv  16
#define NPAD    544
#define MQKV    (Bv*NPAD)      // 4352
#define MS      (Bv*Sv)        // 4096
#define M2      (2*MS)         // 8192

#define WOFF_QKV 0
#define WOFF_WO  1572864
#define WOFF_HW  2097152
#define BOFF_QKV 0
#define BOFF_WO  3072
#define BOFF_HW  4096

// ---------------- scratch (half activations/weights) ---------------------------
__device__ __half g_x[MQKV*Dv];
__device__ __half g_qkv[MQKV*3072];
__device__ __half g_attn[2*MQKV*Dv];
__device__ __half g_h0a[M2*Dv];
__device__ __half g_h0b[M2*Dv];
__device__ __half g_wcvt[4194304];
__device__ float  g_bias[8192];

// ---------------- helpers -------------------------------------------------------
__device__ __forceinline__ uint32_t smem_u32(const void* p) {
    uint32_t a;
    asm("{ .reg .u64 t; cvta.to.shared.u64 t, %1; cvt.u32.u64 %0, t; }"
        : "=r"(a) : "l"(p));
    return a;
}
__device__ __forceinline__ void cpa16(uint32_t s, const void* g) {
    asm volatile("cp.async.cg.shared.global [%0], [%1], 16;" :: "r"(s), "l"(g));
}

// ---------------- prep (4 floats/thread) -------------------------------------------
#define PREP_W4   1048576                       // 4194304/4 weight quads
#define PREP_B    (PREP_W4 + 8192)              // bias scalars
#define PREP_P4   (PREP_B + MQKV*Dv/4)          // pad quads

__global__ void prep_kernel(
    const float* __restrict__ inp,
    const float* __restrict__ lp,  const float* __restrict__ rp,
    const float* __restrict__ Wq0, const float* __restrict__ Wq1,
    const float* __restrict__ Wo0, const float* __restrict__ Wo1,
    const float* __restrict__ Wh0, const float* __restrict__ Wh1,
    const float* __restrict__ bq0, const float* __restrict__ bq1,
    const float* __restrict__ bo0, const float* __restrict__ bo1,
    const float* __restrict__ bh0, const float* __restrict__ bh1)
{
    int t = blockIdx.x * 256 + threadIdx.x;
    if (t < PREP_W4) {
        int i = t * 4;                          // quad start; same row (k%512 <= 508)
        const float* src;
        if (i < WOFF_WO) {
            int n = i >> 9, k = i & 511;
            int d = n >= 1536;
            src = (d ? Wq1 : Wq0) + (n - d * 1536) * 512 + k;
        } else if (i < WOFF_HW) {
            int j = i - WOFF_WO;
            int n = j >> 9, k = j & 511;
            int d = n >= 512;
            src = (d ? Wo1 : Wo0) + (n - d * 512) * 512 + k;
        } else {
            int j = i - WOFF_HW;
            int blk = j >> 19;
            int d = blk >> 1, l = blk & 1;
            int rw = (j >> 9) & 1023, k = j & 511;
            int c = rw >> 1, wh = rw & 1;
            src = (d ? Wh1 : Wh0) + l * 524288 + (wh * 512 + c) * 512 + k;
        }
        float4 v = *(const float4*)src;
        __half2 a = __floats2half2_rn(v.x, v.y);
        __half2 b = __floats2half2_rn(v.z, v.w);
        uint2 u = {*(uint32_t*)&a, *(uint32_t*)&b};
        *(uint2*)(g_wcvt + i) = u;
    } else if (t < PREP_B) {
        int j = t - PREP_W4;
        float v;
        if (j < BOFF_WO) {
            int d = j >= 1536;
            v = (d ? bq1 : bq0)[j - d * 1536];
        } else if (j < BOFF_HW) {
            int jj = j - BOFF_WO;
            int d = jj >= 512;
            v = (d ? bo1 : bo0)[jj - d * 512];
        } else {
            int jj = j - BOFF_HW;
            int blk = jj >> 10;
            int d = blk >> 1, l = blk & 1;
            int r = jj & 1023;
            int c = r >> 1, wh = r & 1;
            v = (d ? bh1 : bh0)[l * 1024 + wh * 512 + c];
        }
        g_bias[j] = v;
    } else if (t < PREP_P4) {
        int idx = (t - PREP_B) * 4;
        int d = idx & (Dv - 1);
        int p = (idx / Dv) % NPAD;
        int b = idx / (Dv * NPAD);
        const float* src;
        if (p < WIDTHv)            src = lp + p * Dv + d;
        else if (p < WIDTHv + Sv)  src = inp + ((size_t)b * Sv + (p - WIDTHv)) * Dv + d;
        else                       src = rp + (p - WIDTHv - Sv) * Dv + d;
        float4 v = *(const float4*)src;
        __half2 a = __floats2half2_rn(v.x, v.y);
        __half2 bb = __floats2half2_rn(v.z, v.w);
        uint2 u = {*(uint32_t*)&a, *(uint32_t*)&bb};
        *(uint2*)(g_x + idx) = u;
    }
}

// ---------------- fp16 mma GEMM: BM=128 BN=64 BK=64, 128 thr, 2-stage --------------
// (round-12 configuration — best measured; do not reshape without new evidence)
#define ABYT   18432
#define BBYT   9216
#define STGB   27648

__global__ __launch_bounds__(128, 4) void gemm_mma(
    const __half* __restrict__ A, const __half* __restrict__ W,
    const float* __restrict__ bias, void* __restrict__ Cout,
    int Nn, int amap, long wstride, int bstride,
    int emode, long total, int copies)
{
    extern __shared__ char dsm[];
    uint32_t sbase = smem_u32(dsm);
    int tid = threadIdx.x;
    int m0 = blockIdx.y * 128, n0 = blockIdx.x * 64;

    if (m0 >= 4096) { W += wstride; bias += bstride; }

    long aoff[8]; int woff[4];
    uint32_t sa[8], sw[4];
#pragma unroll
    for (int i = 0; i < 8; i++) {
        int id = tid + 128 * i;
        int row = id >> 3, seg = id & 7;
        int gm = m0 + row;
        long ar;
        if (amap) {
            int dir = gm >> 12, s = gm & 4095;
            ar = (long)dir * MQKV + (s >> 9) * NPAD + WIDTHv + (s & 511);
        } else ar = gm;
        aoff[i] = ar * 512 + seg * 8;
        sa[i] = (uint32_t)(row * 144 + seg * 16);
    }
#pragma unroll
    for (int i = 0; i < 4; i++) {
        int id = tid + 128 * i;
        int row = id >> 3, seg = id & 7;
        woff[i] = (n0 + row) * 512 + seg * 8;
        sw[i] = (uint32_t)(row * 144 + seg * 16);
    }

#pragma unroll
    for (int s = 0; s < 2; s++) {
        uint32_t ab = sbase + (uint32_t)s * STGB;
#pragma unroll
        for (int i = 0; i < 8; i++) cpa16(ab + sa[i],        A + aoff[i] + s * 64);
#pragma unroll
        for (int i = 0; i < 4; i++) cpa16(ab + ABYT + sw[i], W + woff[i] + s * 64);
        asm volatile("cp.async.commit_group;");
    }

    int wid = tid >> 5, lane = tid & 31;
    int wm = wid >> 1, wn = wid & 1;
    int grp = lane >> 2, tig = lane & 3;

    float acc[4][4][4];
#pragma unroll
    for (int mt = 0; mt < 4; mt++)
#pragma unroll
        for (int nt = 0; nt < 4; nt++)
#pragma unroll
            for (int r = 0; r < 4; r++) acc[mt][nt][r] = 0.f;

    for (int c = 0; c < 8; c++) {
        if (c >= 7) asm volatile("cp.async.wait_group 0;" ::: "memory");
        else        asm volatile("cp.async.wait_group 1;" ::: "memory");
        __syncthreads();

        const uint32_t* asu = (const uint32_t*)(dsm + (size_t)(c & 1) * STGB);
        const uint32_t* wsu = asu + ABYT / 4;

#pragma unroll
        for (int kk = 0; kk < 4; kk++) {
            int kb = tig + kk * 8;
            uint32_t a[4][4], b[4][2];
#pragma unroll
            for (int mt = 0; mt < 4; mt++) {
                int r = wm * 64 + mt * 16 + grp;
                a[mt][0] = asu[r * 36 + kb];
                a[mt][1] = asu[(r + 8) * 36 + kb];
                a[mt][2] = asu[r * 36 + kb + 4];
                a[mt][3] = asu[(r + 8) * 36 + kb + 4];
            }
#pragma unroll
            for (int nt = 0; nt < 4; nt++) {
                int n = wn * 32 + nt * 8 + grp;
                b[nt][0] = wsu[n * 36 + kb];
                b[nt][1] = wsu[n * 36 + kb + 4];
            }
#pragma unroll
            for (int mt = 0; mt < 4; mt++)
#pragma unroll
                for (int nt = 0; nt < 4; nt++) {
                    asm volatile(
                        "mma.sync.aligned.m16n8k16.row.col.f32.f16.f16.f32 "
                        "{%0,%1,%2,%3}, {%4,%5,%6,%7}, {%8,%9}, {%0,%1,%2,%3};"
                        : "+f"(acc[mt][nt][0]), "+f"(acc[mt][nt][1]),
                          "+f"(acc[mt][nt][2]), "+f"(acc[mt][nt][3])
                        : "r"(a[mt][0]), "r"(a[mt][1]), "r"(a[mt][2]), "r"(a[mt][3]),
                          "r"(b[nt][0]), "r"(b[nt][1]));
                }
        }
        __syncthreads();

        if (c + 2 < 8) {
            uint32_t ab = sbase + (uint32_t)(c & 1) * STGB;
            int k0 = (c + 2) * 64;
#pragma unroll
            for (int i = 0; i < 8; i++) cpa16(ab + sa[i],        A + aoff[i] + k0);
#pragma unroll
            for (int i = 0; i < 4; i++) cpa16(ab + ABYT + sw[i], W + woff[i] + k0);
            asm volatile("cp.async.commit_group;");
        }
    }

    if (emode == 0) {
        __half* C = (__half*)Cout;
#pragma unroll
        for (int mt = 0; mt < 4; mt++) {
            int r = m0 + wm * 64 + mt * 16 + grp;
#pragma unroll
            for (int nt = 0; nt < 4; nt++) {
                int col = n0 + wn * 32 + nt * 8 + 2 * tig;
                float b0 = bias[col], b1 = bias[col + 1];
                __half2 p0 = __floats2half2_rn(acc[mt][nt][0] + b0, acc[mt][nt][1] + b1);
                __half2 p1 = __floats2half2_rn(acc[mt][nt][2] + b0, acc[mt][nt][3] + b1);
                *(__half2*)(C + (size_t)r * Nn + col)       = p0;
                *(__half2*)(C + (size_t)(r + 8) * Nn + col) = p1;
            }
        }
    } else {
#pragma unroll
        for (int mt = 0; mt < 4; mt++) {
            int r = m0 + wm * 64 + mt * 16 + grp;
#pragma unroll
            for (int nt = 0; nt < 4; nt++) {
                int col = n0 + wn * 32 + nt * 8 + 2 * tig;
                int cc = col >> 1;
                float b0 = bias[col], b1 = bias[col + 1];
                float nl1 = acc[mt][nt][0] + b0, gv1 = acc[mt][nt][1] + b1;
                float nl2 = acc[mt][nt][2] + b0, gv2 = acc[mt][nt][3] + b1;
                nl1 = nl1 > 0.f ? nl1 : 0.f;
                nl2 = nl2 > 0.f ? nl2 : 0.f;
                float sg1 = 1.f / (1.f + __expf(-gv1));
                float sg2 = 1.f / (1.f + __expf(-gv2));
                float old1 = __half2float(A[(size_t)r * 512 + cc]);
                float old2 = __half2float(A[(size_t)(r + 8) * 512 + cc]);
                float res1 = sg1 * old1 + (1.f - sg1) * nl1;
                float res2 = sg2 * old2 + (1.f - sg2) * nl2;
                if (emode == 1) {
                    __half* C = (__half*)Cout;
                    C[(size_t)r * 512 + cc]       = __float2half_rn(res1);
                    C[(size_t)(r + 8) * 512 + cc] = __float2half_rn(res2);
                } else {
                    float* C = (float*)Cout;
                    int d1 = r >> 12, s1 = r & 4095;
                    int r2 = r + 8;
                    int d2 = r2 >> 12, s2 = r2 & 4095;
                    size_t o1 = (size_t)s1 * 1024 + d1 * 512 + cc;
                    size_t o2 = (size_t)s2 * 1024 + d2 * 512 + cc;
                    C[o1] = res1; C[o2] = res2;
                    if (copies == 2) { C[total + o1] = res1; C[total + o2] = res2; }
                }
            }
        }
    }
}

// ---------------- banded attention: 256-thr blocks, rows [16,528) only --------------
// block = 4 groups x 64 heads; each group handles 2 consecutive query rows.
__device__ __forceinline__ void ld8h(const __half* p, float* f) {
    uint4 u = *(const uint4*)p;
    float2 t;
    t = __half22float2(*(__half2*)&u.x); f[0] = t.x; f[1] = t.y;
    t = __half22float2(*(__half2*)&u.y); f[2] = t.x; f[3] = t.y;
    t = __half22float2(*(__half2*)&u.z); f[4] = t.x; f[5] = t.y;
    t = __half22float2(*(__half2*)&u.w); f[6] = t.x; f[7] = t.y;
}

__global__ __launch_bounds__(256) void attn_kernel() {
    int blk = blockIdx.x;                 // 1024 blocks: dir(2) x b(8) x 64
    int dir = blk >= 512;
    int rem = dir ? blk - 512 : blk;
    int b = rem >> 6;
    int gblk = rem & 63;                  // 8 rows per block
    int sub = threadIdx.x >> 6;           // group 0..3
    int h = threadIdx.x & 63;
    int i0 = WIDTHv + gblk * 8 + sub * 2; // rows 16..527

    const __half* qkv = g_qkv + (size_t)(b * NPAD) * 3072 + dir * 1536 + h * 8;

    float q[2][8];
#pragma unroll
    for (int r = 0; r < 2; r++) ld8h(qkv + (size_t)(i0 + r) * 3072, q[r]);

    int jbase = dir ? i0 : i0 - WIDTHv - 1;

    float sum[2] = {0, 0};
    float o[2][8];
#pragma unroll
    for (int r = 0; r < 2; r++)
#pragma unroll
        for (int d = 0; d < 8; d++) o[r][d] = 0.f;

#pragma unroll
    for (int jidx = 0; jidx < 19; jidx++) {
        int j = jbase + jidx;
        bool jr = (j >= 0) && (j < NPAD);
        float k[8], v[8];
        if (jr) {
            ld8h(qkv + (size_t)j * 3072 + 512,  k);
            ld8h(qkv + (size_t)j * 3072 + 1024, v);
        }
#pragma unroll
        for (int r = 0; r < 2; r++) {
            int jj = jidx - r;
            if (jj >= 0 && jj < 18 && jr) {
                float s = q[r][0]*k[0] + q[r][1]*k[1] + q[r][2]*k[2] + q[r][3]*k[3]
                        + q[r][4]*k[4] + q[r][5]*k[5] + q[r][6]*k[6] + q[r][7]*k[7];
                float p = __expf(s * 0.35355339059327373f);
                sum[r] += p;
#pragma unroll
                for (int d = 0; d < 8; d++) o[r][d] += p * v[d];
            }
        }
    }
#pragma unroll
    for (int r = 0; r < 2; r++) {
        float inv = 1.f / sum[r];
        uint4 u;
        __half2 h0 = __floats2half2_rn(o[r][0] * inv, o[r][1] * inv);
        __half2 h1 = __floats2half2_rn(o[r][2] * inv, o[r][3] * inv);
        __half2 h2 = __floats2half2_rn(o[r][4] * inv, o[r][5] * inv);
        __half2 h3 = __floats2half2_rn(o[r][6] * inv, o[r][7] * inv);
        u.x = *(uint32_t*)&h0; u.y = *(uint32_t*)&h1;
        u.z = *(uint32_t*)&h2; u.w = *(uint32_t*)&h3;
        *(uint4*)(g_attn + ((size_t)dir * MQKV + b * NPAD + i0 + r) * 512 + h * 8) = u;
    }
}

// ---------------- launcher -----------------------------------------------------------
extern "C" void kernel_launch(void* const* d_in, const int* in_sizes, int n_in,
                              void* d_out, int out_size) {
    __half *xp, *qkvp, *attnp, *h0a, *h0b, *wcp;
    float *bp;
    cudaGetSymbolAddress((void**)&xp,   g_x);
    cudaGetSymbolAddress((void**)&qkvp, g_qkv);
    cudaGetSymbolAddress((void**)&attnp,g_attn);
    cudaGetSymbolAddress((void**)&h0a,  g_h0a);
    cudaGetSymbolAddress((void**)&h0b,  g_h0b);
    cudaGetSymbolAddress((void**)&wcp,  g_wcvt);
    cudaGetSymbolAddress((void**)&bp,   g_bias);

    cudaFuncSetAttribute(gemm_mma, cudaFuncAttributeMaxDynamicSharedMemorySize, 55296);

    long total = (long)MS * 1024;
    int copies = ((long)out_size >= 2 * total) ? 2 : 1;

    prep_kernel<<<(PREP_P4 + 255) / 256, 256>>>(
        (const float*)d_in[0], (const float*)d_in[1], (const float*)d_in[2],
        (const float*)d_in[3], (const float*)d_in[7],
        (const float*)d_in[5], (const float*)d_in[9],
        (const float*)d_in[11], (const float*)d_in[13],
        (const float*)d_in[4], (const float*)d_in[8],
        (const float*)d_in[6], (const float*)d_in[10],
        (const float*)d_in[12], (const float*)d_in[14]);

    // QKV both dirs: [4352,512] x [3072,512]^T -> half  (BN=64)
    gemm_mma<<<dim3(48, 34), 128, 55296>>>(
        xp, wcp + WOFF_QKV, bp + BOFF_QKV, qkvp, 3072,
        0, 0, 0, 0, 0, 0);

    // attention both dirs, rows [16,528) only
    attn_kernel<<<1024, 256>>>();

    // Wo batched + slice fuse -> h0a (half)
    gemm_mma<<<dim3(8, 64), 128, 55296>>>(
        attnp, wcp + WOFF_WO, bp + BOFF_WO, h0a, 512,
        1, 262144, 512, 0, 0, 0);

    // highway layer 0 (fused gate): h0a -> h0b (half)
    gemm_mma<<<dim3(16, 64), 128, 55296>>>(
        h0a, wcp + WOFF_HW, bp + BOFF_HW, h0b, 1024,
        0, 1048576, 2048, 1, 0, 0);

    // highway layer 1 (fused gate + scatter): h0b -> d_out (float)
    gemm_mma<<<dim3(16, 64), 128, 55296>>>(
        h0b, wcp + WOFF_HW + 524288, bp + BOFF_HW + 1024, d_out, 1024,
        0, 1048576, 2048, 2, total, copies);
}

// round 14
// speedup vs baseline: 1.8558x; 1.0868x over previous
#include <cuda_runtime.h>
#include <cuda_fp16.h>
#include <cstdint>
#include <math.h>

#define Bv      8
#define Sv      512
#define Dv      512
#define WIDTHv  16
#define NPAD    544
#define MQKV    (Bv*NPAD)      // 4352
#define MS      (Bv*Sv)        // 4096
#define M2      (2*MS)         // 8192

#define WOFF_QKV 0
#define WOFF_WO  1572864
#define WOFF_HW  2097152
#define BOFF_QKV 0
#define BOFF_WO  3072
#define BOFF_HW  4096

// ---------------- scratch (half activations/weights) ---------------------------
__device__ __half g_x[MQKV*Dv];
__device__ __half g_qkv[MQKV*3072];
__device__ __half g_attn[2*MQKV*Dv];
__device__ __half g_h0a[M2*Dv];
__device__ __half g_h0b[M2*Dv];
__device__ __half g_wcvt[4194304];
__device__ float  g_bias[8192];

// ---------------- helpers -------------------------------------------------------
__device__ __forceinline__ uint32_t smem_u32(const void* p) {
    uint32_t a;
    asm("{ .reg .u64 t; cvta.to.shared.u64 t, %1; cvt.u32.u64 %0, t; }"
        : "=r"(a) : "l"(p));
    return a;
}
__device__ __forceinline__ void cpa16(uint32_t s, const void* g) {
    asm volatile("cp.async.cg.shared.global [%0], [%1], 16;" :: "r"(s), "l"(g));
}

// ---------------- prep (4 floats/thread) -------------------------------------------
#define PREP_W4   1048576
#define PREP_B    (PREP_W4 + 8192)
#define PREP_P4   (PREP_B + MQKV*Dv/4)

__global__ void prep_kernel(
    const float* __restrict__ inp,
    const float* __restrict__ lp,  const float* __restrict__ rp,
    const float* __restrict__ Wq0, const float* __restrict__ Wq1,
    const float* __restrict__ Wo0, const float* __restrict__ Wo1,
    const float* __restrict__ Wh0, const float* __restrict__ Wh1,
    const float* __restrict__ bq0, const float* __restrict__ bq1,
    const float* __restrict__ bo0, const float* __restrict__ bo1,
    const float* __restrict__ bh0, const float* __restrict__ bh1)
{
    int t = blockIdx.x * 256 + threadIdx.x;
    if (t < PREP_W4) {
        int i = t * 4;
        const float* src;
        if (i < WOFF_WO) {
            int n = i >> 9, k = i & 511;
            int d = n >= 1536;
            src = (d ? Wq1 : Wq0) + (n - d * 1536) * 512 + k;
        } else if (i < WOFF_HW) {
            int j = i - WOFF_WO;
            int n = j >> 9, k = j & 511;
            int d = n >= 512;
            src = (d ? Wo1 : Wo0) + (n - d * 512) * 512 + k;
        } else {
            int j = i - WOFF_HW;
            int blk = j >> 19;
            int d = blk >> 1, l = blk & 1;
            int rw = (j >> 9) & 1023, k = j & 511;
            int c = rw >> 1, wh = rw & 1;
            src = (d ? Wh1 : Wh0) + l * 524288 + (wh * 512 + c) * 512 + k;
        }
        float4 v = *(const float4*)src;
        __half2 a = __floats2half2_rn(v.x, v.y);
        __half2 b = __floats2half2_rn(v.z, v.w);
        uint2 u = {*(uint32_t*)&a, *(uint32_t*)&b};
        *(uint2*)(g_wcvt + i) = u;
    } else if (t < PREP_B) {
        int j = t - PREP_W4;
        float v;
        if (j < BOFF_WO) {
            int d = j >= 1536;
            v = (d ? bq1 : bq0)[j - d * 1536];
        } else if (j < BOFF_HW) {
            int jj = j - BOFF_WO;
            int d = jj >= 512;
            v = (d ? bo1 : bo0)[jj - d * 512];
        } else {
            int jj = j - BOFF_HW;
            int blk = jj >> 10;
            int d = blk >> 1, l = blk & 1;
            int r = jj & 1023;
            int c = r >> 1, wh = r & 1;
            v = (d ? bh1 : bh0)[l * 1024 + wh * 512 + c];
        }
        g_bias[j] = v;
    } else if (t < PREP_P4) {
        int idx = (t - PREP_B) * 4;
        int d = idx & (Dv - 1);
        int p = (idx / Dv) % NPAD;
        int b = idx / (Dv * NPAD);
        const float* src;
        if (p < WIDTHv)            src = lp + p * Dv + d;
        else if (p < WIDTHv + Sv)  src = inp + ((size_t)b * Sv + (p - WIDTHv)) * Dv + d;
        else                       src = rp + (p - WIDTHv - Sv) * Dv + d;
        float4 v = *(const float4*)src;
        __half2 a = __floats2half2_rn(v.x, v.y);
        __half2 bb = __floats2half2_rn(v.z, v.w);
        uint2 u = {*(uint32_t*)&a, *(uint32_t*)&bb};
        *(uint2*)(g_x + idx) = u;
    }
}

// ---------------- fp16 mma GEMM: BM=128 BN=64 BK=64, 128 thr, 2-stage --------------
// Single-direction launches. ncol0 = output column base (W rows stay local).
// amap: A row = (gm/512)*544 + 16 + gm%512. emode: 0 bias store; 1 hw gate ->
// C[r*512+cc]; 2 hw gate -> d_out scatter at coloff.
#define ABYT   18432
#define STGB   27648

__global__ __launch_bounds__(128, 4) void gemm_mma(
    const __half* __restrict__ A, const __half* __restrict__ W,
    const float* __restrict__ bias, void* __restrict__ Cout,
    int Nn, int amap, int ncol0,
    int emode, long total, int copies, int coloff)
{
    extern __shared__ char dsm[];
    uint32_t sbase = smem_u32(dsm);
    int tid = threadIdx.x;
    int m0 = blockIdx.y * 128, n0 = blockIdx.x * 64;

    long aoff[8]; int woff[4];
    uint32_t sa[8], sw[4];
#pragma unroll
    for (int i = 0; i < 8; i++) {
        int id = tid + 128 * i;
        int row = id >> 3, seg = id & 7;
        int gm = m0 + row;
        long ar = amap ? ((long)(gm >> 9) * NPAD + WIDTHv + (gm & 511)) : (long)gm;
        aoff[i] = ar * 512 + seg * 8;
        sa[i] = (uint32_t)(row * 144 + seg * 16);
    }
#pragma unroll
    for (int i = 0; i < 4; i++) {
        int id = tid + 128 * i;
        int row = id >> 3, seg = id & 7;
        woff[i] = (n0 + row) * 512 + seg * 8;
        sw[i] = (uint32_t)(row * 144 + seg * 16);
    }

#pragma unroll
    for (int s = 0; s < 2; s++) {
        uint32_t ab = sbase + (uint32_t)s * STGB;
#pragma unroll
        for (int i = 0; i < 8; i++) cpa16(ab + sa[i],        A + aoff[i] + s * 64);
#pragma unroll
        for (int i = 0; i < 4; i++) cpa16(ab + ABYT + sw[i], W + woff[i] + s * 64);
        asm volatile("cp.async.commit_group;");
    }

    int wid = tid >> 5, lane = tid & 31;
    int wm = wid >> 1, wn = wid & 1;
    int grp = lane >> 2, tig = lane & 3;

    float acc[4][4][4];
#pragma unroll
    for (int mt = 0; mt < 4; mt++)
#pragma unroll
        for (int nt = 0; nt < 4; nt++)
#pragma unroll
            for (int r = 0; r < 4; r++) acc[mt][nt][r] = 0.f;

    for (int c = 0; c < 8; c++) {
        if (c >= 7) asm volatile("cp.async.wait_group 0;" ::: "memory");
        else        asm volatile("cp.async.wait_group 1;" ::: "memory");
        __syncthreads();

        const uint32_t* asu = (const uint32_t*)(dsm + (size_t)(c & 1) * STGB);
        const uint32_t* wsu = asu + ABYT / 4;

#pragma unroll
        for (int kk = 0; kk < 4; kk++) {
            int kb = tig + kk * 8;
            uint32_t a[4][4], b[4][2];
#pragma unroll
            for (int mt = 0; mt < 4; mt++) {
                int r = wm * 64 + mt * 16 + grp;
                a[mt][0] = asu[r * 36 + kb];
                a[mt][1] = asu[(r + 8) * 36 + kb];
                a[mt][2] = asu[r * 36 + kb + 4];
                a[mt][3] = asu[(r + 8) * 36 + kb + 4];
            }
#pragma unroll
            for (int nt = 0; nt < 4; nt++) {
                int n = wn * 32 + nt * 8 + grp;
                b[nt][0] = wsu[n * 36 + kb];
                b[nt][1] = wsu[n * 36 + kb + 4];
            }
#pragma unroll
            for (int mt = 0; mt < 4; mt++)
#pragma unroll
                for (int nt = 0; nt < 4; nt++) {
                    asm volatile(
                        "mma.sync.aligned.m16n8k16.row.col.f32.f16.f16.f32 "
                        "{%0,%1,%2,%3}, {%4,%5,%6,%7}, {%8,%9}, {%0,%1,%2,%3};"
                        : "+f"(acc[mt][nt][0]), "+f"(acc[mt][nt][1]),
                          "+f"(acc[mt][nt][2]), "+f"(acc[mt][nt][3])
                        : "r"(a[mt][0]), "r"(a[mt][1]), "r"(a[mt][2]), "r"(a[mt][3]),
                          "r"(b[nt][0]), "r"(b[nt][1]));
                }
        }
        __syncthreads();

        if (c + 2 < 8) {
            uint32_t ab = sbase + (uint32_t)(c & 1) * STGB;
            int k0 = (c + 2) * 64;
#pragma unroll
            for (int i = 0; i < 8; i++) cpa16(ab + sa[i],        A + aoff[i] + k0);
#pragma unroll
            for (int i = 0; i < 4; i++) cpa16(ab + ABYT + sw[i], W + woff[i] + k0);
            asm volatile("cp.async.commit_group;");
        }
    }

    if (emode == 0) {
        __half* C = (__half*)Cout;
#pragma unroll
        for (int mt = 0; mt < 4; mt++) {
            int r = m0 + wm * 64 + mt * 16 + grp;
#pragma unroll
            for (int nt = 0; nt < 4; nt++) {
                int cl = n0 + wn * 32 + nt * 8 + 2 * tig;
                float b0 = bias[cl], b1 = bias[cl + 1];
                __half2 p0 = __floats2half2_rn(acc[mt][nt][0] + b0, acc[mt][nt][1] + b1);
                __half2 p1 = __floats2half2_rn(acc[mt][nt][2] + b0, acc[mt][nt][3] + b1);
                *(__half2*)(C + (size_t)r * Nn + ncol0 + cl)       = p0;
                *(__half2*)(C + (size_t)(r + 8) * Nn + ncol0 + cl) = p1;
            }
        }
    } else {
#pragma unroll
        for (int mt = 0; mt < 4; mt++) {
            int r = m0 + wm * 64 + mt * 16 + grp;
#pragma unroll
            for (int nt = 0; nt < 4; nt++) {
                int cl = n0 + wn * 32 + nt * 8 + 2 * tig;
                int cc = cl >> 1;
                float b0 = bias[cl], b1 = bias[cl + 1];
                float nl1 = acc[mt][nt][0] + b0, gv1 = acc[mt][nt][1] + b1;
                float nl2 = acc[mt][nt][2] + b0, gv2 = acc[mt][nt][3] + b1;
                nl1 = nl1 > 0.f ? nl1 : 0.f;
                nl2 = nl2 > 0.f ? nl2 : 0.f;
                float sg1 = 1.f / (1.f + __expf(-gv1));
                float sg2 = 1.f / (1.f + __expf(-gv2));
                float old1 = __half2float(A[(size_t)r * 512 + cc]);
                float old2 = __half2float(A[(size_t)(r + 8) * 512 + cc]);
                float res1 = sg1 * old1 + (1.f - sg1) * nl1;
                float res2 = sg2 * old2 + (1.f - sg2) * nl2;
                if (emode == 1) {
                    __half* C = (__half*)Cout;
                    C[(size_t)r * 512 + cc]       = __float2half_rn(res1);
                    C[(size_t)(r + 8) * 512 + cc] = __float2half_rn(res2);
                } else {
                    float* C = (float*)Cout;
                    size_t o1 = (size_t)r * 1024 + coloff + cc;
                    size_t o2 = (size_t)(r + 8) * 1024 + coloff + cc;
                    C[o1] = res1; C[o2] = res2;
                    if (copies == 2) { C[total + o1] = res1; C[total + o2] = res2; }
                }
            }
        }
    }
}

// ---------------- banded attention: per-dir, 256-thr blocks, rows [16,528) ----------
__device__ __forceinline__ void ld8h(const __half* p, float* f) {
    uint4 u = *(const uint4*)p;
    float2 t;
    t = __half22float2(*(__half2*)&u.x); f[0] = t.x; f[1] = t.y;
    t = __half22float2(*(__half2*)&u.y); f[2] = t.x; f[3] = t.y;
    t = __half22float2(*(__half2*)&u.z); f[4] = t.x; f[5] = t.y;
    t = __half22float2(*(__half2*)&u.w); f[6] = t.x; f[7] = t.y;
}

__global__ __launch_bounds__(256) void attn_kernel(int dir) {
    int rem = blockIdx.x;                 // 512 blocks: b(8) x 64
    int b = rem >> 6;
    int gblk = rem & 63;
    int sub = threadIdx.x >> 6;
    int h = threadIdx.x & 63;
    int i0 = WIDTHv + gblk * 8 + sub * 2;

    const __half* qkv = g_qkv + (size_t)(b * NPAD) * 3072 + dir * 1536 + h * 8;

    float q[2][8];
#pragma unroll
    for (int r = 0; r < 2; r++) ld8h(qkv + (size_t)(i0 + r) * 3072, q[r]);

    int jbase = dir ? i0 : i0 - WIDTHv - 1;

    float sum[2] = {0, 0};
    float o[2][8];
#pragma unroll
    for (int r = 0; r < 2; r++)
#pragma unroll
        for (int d = 0; d < 8; d++) o[r][d] = 0.f;

#pragma unroll
    for (int jidx = 0; jidx < 19; jidx++) {
        int j = jbase + jidx;
        bool jr = (j >= 0) && (j < NPAD);
        float k[8], v[8];
        if (jr) {
            ld8h(qkv + (size_t)j * 3072 + 512,  k);
            ld8h(qkv + (size_t)j * 3072 + 1024, v);
        }
#pragma unroll
        for (int r = 0; r < 2; r++) {
            int jj = jidx - r;
            if (jj >= 0 && jj < 18 && jr) {
                float s = q[r][0]*k[0] + q[r][1]*k[1] + q[r][2]*k[2] + q[r][3]*k[3]
                        + q[r][4]*k[4] + q[r][5]*k[5] + q[r][6]*k[6] + q[r][7]*k[7];
                float p = __expf(s * 0.35355339059327373f);
                sum[r] += p;
#pragma unroll
                for (int d = 0; d < 8; d++) o[r][d] += p * v[d];
            }
        }
    }
#pragma unroll
    for (int r = 0; r < 2; r++) {
        float inv = 1.f / sum[r];
        uint4 u;
        __half2 h0 = __floats2half2_rn(o[r][0] * inv, o[r][1] * inv);
        __half2 h1 = __floats2half2_rn(o[r][2] * inv, o[r][3] * inv);
        __half2 h2 = __floats2half2_rn(o[r][4] * inv, o[r][5] * inv);
        __half2 h3 = __floats2half2_rn(o[r][6] * inv, o[r][7] * inv);
        u.x = *(uint32_t*)&h0; u.y = *(uint32_t*)&h1;
        u.z = *(uint32_t*)&h2; u.w = *(uint32_t*)&h3;
        *(uint4*)(g_attn + ((size_t)dir * MQKV + b * NPAD + i0 + r) * 512 + h * 8) = u;
    }
}

// ---------------- launcher: two independent per-dir pipelines on two streams -------
extern "C" void kernel_launch(void* const* d_in, const int* in_sizes, int n_in,
                              void* d_out, int out_size) {
    __half *xp, *qkvp, *attnp, *h0a, *h0b, *wcp;
    float *bp;
    cudaGetSymbolAddress((void**)&xp,   g_x);
    cudaGetSymbolAddress((void**)&qkvp, g_qkv);
    cudaGetSymbolAddress((void**)&attnp,g_attn);
    cudaGetSymbolAddress((void**)&h0a,  g_h0a);
    cudaGetSymbolAddress((void**)&h0b,  g_h0b);
    cudaGetSymbolAddress((void**)&wcp,  g_wcvt);
    cudaGetSymbolAddress((void**)&bp,   g_bias);

    static cudaStream_t s1 = nullptr;
    static cudaEvent_t evF = nullptr, evJ = nullptr;
    if (!s1) {
        cudaStreamCreateWithFlags(&s1, cudaStreamNonBlocking);
        cudaEventCreateWithFlags(&evF, cudaEventDisableTiming);
        cudaEventCreateWithFlags(&evJ, cudaEventDisableTiming);
        cudaFuncSetAttribute(gemm_mma, cudaFuncAttributeMaxDynamicSharedMemorySize, 55296);
    }

    long total = (long)MS * 1024;
    int copies = ((long)out_size >= 2 * total) ? 2 : 1;

    prep_kernel<<<(PREP_P4 + 255) / 256, 256>>>(
        (const float*)d_in[0], (const float*)d_in[1], (const float*)d_in[2],
        (const float*)d_in[3], (const float*)d_in[7],
        (const float*)d_in[5], (const float*)d_in[9],
        (const float*)d_in[11], (const float*)d_in[13],
        (const float*)d_in[4], (const float*)d_in[8],
        (const float*)d_in[6], (const float*)d_in[10],
        (const float*)d_in[12], (const float*)d_in[14]);

    cudaEventRecord(evF, 0);
    cudaStreamWaitEvent(s1, evF, 0);

    for (int dir = 0; dir < 2; dir++) {
        cudaStream_t st = dir ? s1 : 0;
        size_t adoff = (size_t)dir * MQKV * 512;
        size_t hdoff = (size_t)dir * MS * 512;

        // QKV_d: [4352,512] x [1536,512]^T -> g_qkv cols [dir*1536, +1536)
        gemm_mma<<<dim3(24, 34), 128, 55296, st>>>(
            xp, wcp + (size_t)dir * 786432, bp + dir * 1536, qkvp, 3072,
            0, dir * 1536, 0, 0, 0, 0);

        attn_kernel<<<512, 256, 0, st>>>(dir);

        // Wo_d + slice fuse -> h0a[dir]
        gemm_mma<<<dim3(8, 32), 128, 55296, st>>>(
            attnp + adoff, wcp + WOFF_WO + (size_t)dir * 262144,
            bp + BOFF_WO + dir * 512, h0a + hdoff, 512,
            1, 0, 0, 0, 0, 0);

        // hw0_d (fused gate): h0a[dir] -> h0b[dir]
        gemm_mma<<<dim3(16, 32), 128, 55296, st>>>(
            h0a + hdoff, wcp + WOFF_HW + (size_t)(dir * 2) * 524288,
            bp + BOFF_HW + dir * 2048, h0b + hdoff, 1024,
            0, 0, 1, 0, 0, 0);

        // hw1_d (fused gate + scatter): h0b[dir] -> d_out cols [dir*512, +512)
        gemm_mma<<<dim3(16, 32), 128, 55296, st>>>(
            h0b + hdoff, wcp + WOFF_HW + (size_t)(dir * 2 + 1) * 524288,
            bp + BOFF_HW + dir * 2048 + 1024, d_out, 1024,
            0, 0, 2, total, copies, dir * 512);
    }

    cudaEventRecord(evJ, s1);
    cudaStreamWaitEvent(0, evJ, 0);
}